// round 15
// baseline (speedup 1.0000x reference)
#include <cuda_runtime.h>
#include <stdint.h>
#include <math.h>

#define NE 320000
#define NA 10000
#define CAP 128            // per-atom bin capacity (P(deg>128) ~ e^-81)
#define RCV 5.0f
#define TBL_N 512
#define PIF 3.14159265358979323846f
#define EDGE_BLOCKS (NE / 128)     // 2500
#define TBL_BLOCKS 257             // 2 rows per block -> 514 >= 513

// ---- scratch (device globals; zero-initialized at load; no runtime allocation) ----
__device__ float4 g_pre[(size_t)NA * CAP];      // per edge (binned): hx,hy,hz, u+1024*spc
// table row (256B stride): [0:32) = 8r x float4 (k=0..3), [32:48) = 8r x float2 (k=4,5)
__device__ float  g_tbl[(TBL_N + 1) * 64];
__device__ int    g_cursor[NA];                 // starts 0; k_atom_mlp resets to 0 each call

__device__ __forceinline__ float silu(float x) { return x / (1.0f + __expf(-x)); }

// ---- pass 1: edge blocks (0..2499) + table blocks (2500..2756) in one grid ----
__global__ __launch_bounds__(128) void k_edge_tbl(
    const float* __restrict__ rij, const int* __restrict__ species,
    const int* __restrict__ fa, const int* __restrict__ sa,
    const float* __restrict__ Wr1, const float* __restrict__ br1,
    const float* __restrict__ Wr2, const float* __restrict__ br2)
{
    int t = threadIdx.x;

    if (blockIdx.x >= EDGE_BLOCKS) {
        // ---- table build: 2 rows per block, 64 threads per row ----
        __shared__ float sh[2][64];
        int b = blockIdx.x - EDGE_BLOCKS;
        int half = t >> 6, i = t & 63;
        int idx = b * 2 + half;
        bool ok = (idx <= TBL_N);
        float fc = 0.f, h = 0.f;
        if (ok) {
            float d = idx * (RCV / TBL_N);
            float dd = fmaxf(d, 1e-6f);
            fc = 0.5f * (cosf(PIF * d * (1.0f / RCV)) + 1.0f);
            float a1 = PIF * dd * (1.0f / RCV);
            float s1, c1;
            sincosf(a1, &s1, &c1);
            float pref = sqrtf(2.0f / RCV) / dd;
            float bes[8];
            float prev = 0.0f, cur = s1, twoc = 2.0f * c1;
            bes[0] = cur * pref;
#pragma unroll
            for (int k = 1; k < 8; k++) { float nxt = twoc * cur - prev; bes[k] = nxt * pref; prev = cur; cur = nxt; }
            h = br1[i];
#pragma unroll
            for (int k = 0; k < 8; k++) h = fmaf(bes[k], __ldg(&Wr1[k * 64 + i]), h);
            h = silu(h);
        }
        sh[half][i] = h;
        __syncthreads();
        if (ok && i < 48) {
            float acc = br2[i];
            const float* hh = sh[half];
#pragma unroll 8
            for (int k = 0; k < 64; k++) acc = fmaf(hh[k], __ldg(&Wr2[k * 48 + i]), acc);
            // output j = 8k+r: k<4 -> idx*64 + r*4 + k ; k>=4 -> idx*64 + 32 + r*2 + (k-4)
            int rr = i & 7, kk = i >> 3;
            int off = (kk < 4) ? (rr * 4 + kk) : (32 + rr * 2 + (kk - 4));
            g_tbl[(size_t)idx * 64 + off] = silu(acc) * fc;
        }
        return;
    }

    // ---- edge path: 16B payload, no transpose needed ----
    int e = blockIdx.x * 128 + t;
    float x = rij[3 * e + 0], y = rij[3 * e + 1], z = rij[3 * e + 2];
    float d = sqrtf(x * x + y * y + z * z + 1e-12f);
    float inv = 1.0f / d;
    float u = d * ((float)TBL_N / RCV);
    int spc = species[sa[e]];
    float w = u + 1024.0f * (float)spc;
    int a = fa[e];
    int row = a * CAP + atomicAdd(&g_cursor[a], 1);
    g_pre[row] = make_float4(x * inv, y * inv, z * inv, w);
}

// ---- pass 2: warp-per-atom accumulate; CTA-batched MLP (2 weight-reading groups) ----
__global__ __launch_bounds__(256, 4) void k_atom_mlp(
    const float* __restrict__ Wa1, const float* __restrict__ ba1,
    const float* __restrict__ Wa2, const float* __restrict__ ba2,
    const float* __restrict__ Wa3, const float* __restrict__ ba3,
    const float* __restrict__ Ws1, const float* __restrict__ bs1,
    const float* __restrict__ Ws2, const float* __restrict__ bs2,
    float* __restrict__ out)
{
    __shared__ __align__(16) float sfeat[8][192];
    __shared__ __align__(16) float sh1[8][64];
    __shared__ float sW2[4096];
    __shared__ float sW3[64], sB1[64], sB2[64];
    __shared__ float sem[12];
    __shared__ float spart[4][4];

    int t = threadIdx.x, warp = t >> 5, lane = t & 31;
    for (int i = t; i < 4096; i += 256) sW2[i] = Wa2[i];
    if (t < 64) { sW3[t] = Wa3[t]; sB1[t] = ba1[t]; sB2[t] = ba2[t]; }
    if (t < 12) {   // species embedding: 3 species x 4 outputs
        int spq = t >> 2, so = t & 3;
        float a = bs2[so];
#pragma unroll
        for (int i = 0; i < 16; i++)
            a = fmaf(tanhf(Ws1[spq * 16 + i] + bs1[i]), Ws2[i * 4 + so], a);
        sem[t] = a;
    }
    __syncthreads();

    int n = blockIdx.x * 8 + warp;           // grid is exactly NA/8
    int cnt = g_cursor[n];
    if (lane == 0) g_cursor[n] = 0;          // reset for next graph replay
    int r = lane & 7, s = lane >> 3;
    float acc[35];
#pragma unroll
    for (int c = 0; c < 35; c++) acc[c] = 0.f;
    float lin = 0.f;
    const float4* base = g_pre + (size_t)n * CAP;
    // per-lane species-embedding values in registers
    float se0 = sem[s], se1 = sem[4 + s], se2 = sem[8 + s];

    // depth-2 register prefetch (g_pre is L2-resident; occupancy hides the rest)
    float4 va[2];
#pragma unroll
    for (int q = 0; q < 2; q++)
        va[q] = (q < cnt) ? __ldg(base + q) : make_float4(0.f, 0.f, 0.f, 0.f);

    for (int i = 0; i < cnt; i++) {
        float4 p = va[i & 1];
        if (i + 2 < cnt) va[i & 1] = __ldg(base + i + 2);

        // decode this edge, inline table lerp (each load hits exactly one 128B line)
        int spc = (int)(p.w * (1.0f / 1024.0f));
        float u0 = fmaf(-1024.0f, (float)spc, p.w);
        int ir = min((int)u0, TBL_N - 1);
        float fr = u0 - (float)ir;
        const float* t0 = g_tbl + (size_t)ir * 64;
        float4 ta4 = *(const float4*)(t0 + 4 * r);
        float2 ta2 = *(const float2*)(t0 + 32 + 2 * r);
        float4 tb4 = *(const float4*)(t0 + 64 + 4 * r);
        float2 tb2 = *(const float2*)(t0 + 96 + 2 * r);
        float sj = (spc == 0) ? se0 : ((spc == 1) ? se1 : se2);

        float F0 = fmaf(fr, tb4.x - ta4.x, ta4.x);
        float F1 = fmaf(fr, tb4.y - ta4.y, ta4.y);
        float F2 = fmaf(fr, tb4.z - ta4.z, ta4.z);
        float F3 = fmaf(fr, tb4.w - ta4.w, ta4.w);
        float F4 = fmaf(fr, tb2.x - ta2.x, ta2.x);
        float F5 = fmaf(fr, tb2.y - ta2.y, ta2.y);

        float hx = p.x, hy = p.y, hz = p.z;
        lin = fmaf(F0, sj, lin);
        float m0 = F1 * sj, m1 = F2 * sj, m2 = F3 * sj, m3 = F4 * sj, m4 = F5 * sj;

        // monomial recursion (order matches reference term enumeration)
        float zz = hz * hz, yz = hy * hz, yy = hy * hy, xz = hx * hz, xy = hx * hy, xx = hx * hx;
        float z3 = hz * zz, yz2 = hy * zz, y2z = yy * hz, y3 = hy * yy,
              xz2 = hx * zz, xyz = hx * yz, xy2 = hx * yy, x2z = xx * hz, x2y = xx * hy, x3 = hx * xx;
        acc[0]  = fmaf(m0, 1.f, acc[0]);
        acc[1]  = fmaf(m1, hz, acc[1]);  acc[2]  = fmaf(m1, hy, acc[2]);  acc[3]  = fmaf(m1, hx, acc[3]);
        acc[4]  = fmaf(m2, zz, acc[4]);  acc[5]  = fmaf(m2, yz, acc[5]);  acc[6]  = fmaf(m2, yy, acc[6]);
        acc[7]  = fmaf(m2, xz, acc[7]);  acc[8]  = fmaf(m2, xy, acc[8]);  acc[9]  = fmaf(m2, xx, acc[9]);
        acc[10] = fmaf(m3, z3, acc[10]);  acc[11] = fmaf(m3, yz2, acc[11]);
        acc[12] = fmaf(m3, y2z, acc[12]); acc[13] = fmaf(m3, y3, acc[13]);
        acc[14] = fmaf(m3, xz2, acc[14]); acc[15] = fmaf(m3, xyz, acc[15]);
        acc[16] = fmaf(m3, xy2, acc[16]); acc[17] = fmaf(m3, x2z, acc[17]);
        acc[18] = fmaf(m3, x2y, acc[18]); acc[19] = fmaf(m3, x3, acc[19]);
        acc[20] = fmaf(m4, hz * z3, acc[20]);  acc[21] = fmaf(m4, hy * z3, acc[21]);
        acc[22] = fmaf(m4, yy * zz, acc[22]);  acc[23] = fmaf(m4, y3 * hz, acc[23]);
        acc[24] = fmaf(m4, hy * y3, acc[24]);  acc[25] = fmaf(m4, hx * z3, acc[25]);
        acc[26] = fmaf(m4, hx * yz2, acc[26]); acc[27] = fmaf(m4, hx * y2z, acc[27]);
        acc[28] = fmaf(m4, hx * y3, acc[28]);  acc[29] = fmaf(m4, xx * zz, acc[29]);
        acc[30] = fmaf(m4, xx * yz, acc[30]);  acc[31] = fmaf(m4, xx * yy, acc[31]);
        acc[32] = fmaf(m4, x3 * hz, acc[32]);  acc[33] = fmaf(m4, x3 * hy, acc[33]);
        acc[34] = fmaf(m4, hx * x3, acc[34]);
    }

    // contract squared moments into feat[192] (per-warp smem)
    float* sf = sfeat[warp];
    sf[r * 4 + s] = lin;
    sf[(8 + r) * 4 + s] = acc[0] * acc[0];
    sf[(16 + r) * 4 + s] = acc[1] * acc[1] + acc[2] * acc[2] + acc[3] * acc[3];
    sf[(24 + r) * 4 + s] = acc[4] * acc[4] + 2.f * acc[5] * acc[5] + acc[6] * acc[6]
                         + 2.f * acc[7] * acc[7] + 2.f * acc[8] * acc[8] + acc[9] * acc[9];
    const float nm3[10] = {1, 3, 3, 1, 3, 6, 3, 3, 3, 1};
    float f3 = 0.f;
#pragma unroll
    for (int c = 0; c < 10; c++) f3 += nm3[c] * acc[10 + c] * acc[10 + c];
    sf[(32 + r) * 4 + s] = f3;
    const float nm4[15] = {1, 4, 6, 4, 1, 4, 12, 12, 4, 6, 12, 6, 4, 4, 1};
    float f4 = 0.f;
#pragma unroll
    for (int c = 0; c < 15; c++) f4 += nm4[c] * acc[20 + c] * acc[20 + c];
    sf[(40 + r) * 4 + s] = f4;
    __syncthreads();

    // ---- CTA-batched MLP: threads 0-127; group g=t>>6 owns atoms 4g..4g+3, neuron j ----
    if (t < 128) {
        int j = t & 63, g = t >> 6;
        int a0 = 4 * g;

        // layer 1: 192 -> 64 (W1 read 2x per CTA instead of 4x)
        float b1 = sB1[j];
        float h0 = b1, h1 = b1, h2 = b1, h3 = b1;
        const float4* fa4 = (const float4*)sfeat[a0 + 0];
        const float4* fb4 = (const float4*)sfeat[a0 + 1];
        const float4* fc4 = (const float4*)sfeat[a0 + 2];
        const float4* fd4 = (const float4*)sfeat[a0 + 3];
#pragma unroll 2
        for (int f4i = 0; f4i < 48; f4i++) {
            float4 qa = fa4[f4i], qb = fb4[f4i], qc = fc4[f4i], qd = fd4[f4i];
            int fb = f4i * 4;
            float w0 = __ldg(&Wa1[(fb + 0) * 64 + j]);
            float w1 = __ldg(&Wa1[(fb + 1) * 64 + j]);
            float w2 = __ldg(&Wa1[(fb + 2) * 64 + j]);
            float w3 = __ldg(&Wa1[(fb + 3) * 64 + j]);
            h0 = fmaf(qa.x, w0, h0); h1 = fmaf(qb.x, w0, h1); h2 = fmaf(qc.x, w0, h2); h3 = fmaf(qd.x, w0, h3);
            h0 = fmaf(qa.y, w1, h0); h1 = fmaf(qb.y, w1, h1); h2 = fmaf(qc.y, w1, h2); h3 = fmaf(qd.y, w1, h3);
            h0 = fmaf(qa.z, w2, h0); h1 = fmaf(qb.z, w2, h1); h2 = fmaf(qc.z, w2, h2); h3 = fmaf(qd.z, w2, h3);
            h0 = fmaf(qa.w, w3, h0); h1 = fmaf(qb.w, w3, h1); h2 = fmaf(qc.w, w3, h2); h3 = fmaf(qd.w, w3, h3);
        }
        sh1[a0 + 0][j] = silu(h0);
        sh1[a0 + 1][j] = silu(h1);
        sh1[a0 + 2][j] = silu(h2);
        sh1[a0 + 3][j] = silu(h3);
    }
    __syncthreads();

    if (t < 128) {
        int j = t & 63, g = t >> 6;
        int a0 = 4 * g;
        // layer 2: 64 -> 64 (all from smem, read 2x per CTA)
        float b2 = sB2[j];
        float g0 = b2, g1 = b2, g2 = b2, g3 = b2;
        const float4* ha4 = (const float4*)sh1[a0 + 0];
        const float4* hb4 = (const float4*)sh1[a0 + 1];
        const float4* hc4 = (const float4*)sh1[a0 + 2];
        const float4* hd4 = (const float4*)sh1[a0 + 3];
#pragma unroll 2
        for (int k4 = 0; k4 < 16; k4++) {
            float4 qa = ha4[k4], qb = hb4[k4], qc = hc4[k4], qd = hd4[k4];
            int kb = k4 * 4;
            float w0 = sW2[(kb + 0) * 64 + j];
            float w1 = sW2[(kb + 1) * 64 + j];
            float w2 = sW2[(kb + 2) * 64 + j];
            float w3 = sW2[(kb + 3) * 64 + j];
            g0 = fmaf(qa.x, w0, g0); g1 = fmaf(qb.x, w0, g1); g2 = fmaf(qc.x, w0, g2); g3 = fmaf(qd.x, w0, g3);
            g0 = fmaf(qa.y, w1, g0); g1 = fmaf(qb.y, w1, g1); g2 = fmaf(qc.y, w1, g2); g3 = fmaf(qd.y, w1, g3);
            g0 = fmaf(qa.z, w2, g0); g1 = fmaf(qb.z, w2, g1); g2 = fmaf(qc.z, w2, g2); g3 = fmaf(qd.z, w2, g3);
            g0 = fmaf(qa.w, w3, g0); g1 = fmaf(qb.w, w3, g1); g2 = fmaf(qc.w, w3, g2); g3 = fmaf(qd.w, w3, g3);
        }
        float w3j = sW3[j];
        float p0 = silu(g0) * w3j, p1 = silu(g1) * w3j, p2 = silu(g2) * w3j, p3 = silu(g3) * w3j;
#pragma unroll
        for (int off = 16; off; off >>= 1) {
            p0 += __shfl_down_sync(0xffffffffu, p0, off);
            p1 += __shfl_down_sync(0xffffffffu, p1, off);
            p2 += __shfl_down_sync(0xffffffffu, p2, off);
            p3 += __shfl_down_sync(0xffffffffu, p3, off);
        }
        if (lane == 0) {
            spart[warp][0] = p0; spart[warp][1] = p1;
            spart[warp][2] = p2; spart[warp][3] = p3;
        }
    }
    __syncthreads();
    if (t < 8)
        out[blockIdx.x * 8 + t] = spart[(t >> 2) * 2][t & 3]
                                + spart[(t >> 2) * 2 + 1][t & 3] + ba3[0];
}

extern "C" void kernel_launch(void* const* d_in, const int* in_sizes, int n_in,
                              void* d_out, int out_size) {
    const float* rij = (const float*)d_in[0];
    const int* species = (const int*)d_in[1];
    const int* fa = (const int*)d_in[2];
    const int* sa = (const int*)d_in[3];
    const float* Wr1 = (const float*)d_in[4];
    const float* br1 = (const float*)d_in[5];
    const float* Wr2 = (const float*)d_in[6];
    const float* br2 = (const float*)d_in[7];
    const float* Ws1 = (const float*)d_in[8];
    const float* bs1 = (const float*)d_in[9];
    const float* Ws2 = (const float*)d_in[10];
    const float* bs2 = (const float*)d_in[11];
    const float* Wa1 = (const float*)d_in[12];
    const float* ba1 = (const float*)d_in[13];
    const float* Wa2 = (const float*)d_in[14];
    const float* ba2 = (const float*)d_in[15];
    const float* Wa3 = (const float*)d_in[16];
    const float* ba3 = (const float*)d_in[17];
    float* out = (float*)d_out;

    k_edge_tbl<<<EDGE_BLOCKS + TBL_BLOCKS, 128>>>(rij, species, fa, sa,
                                                  Wr1, br1, Wr2, br2);
    k_atom_mlp<<<NA / 8, 256>>>(Wa1, ba1, Wa2, ba2, Wa3, ba3,
                                Ws1, bs1, Ws2, bs2, out);
}

// round 16
// speedup vs baseline: 1.1533x; 1.1533x over previous
#include <cuda_runtime.h>
#include <stdint.h>
#include <math.h>

#define NE 320000
#define NA 10000
#define CAP 128            // per-atom bin capacity (P(deg>128) ~ e^-81)
#define RCV 5.0f
#define TBL_N 512
#define PIF 3.14159265358979323846f
#define EDGE_BLOCKS (NE / 128)     // 2500
#define TBL_BLOCKS 257             // 2 rows per block -> 514 >= 513
#define ATOM_CTAS 592              // exactly 4 CTAs/SM x 148 SMs

// ---- scratch (device globals; zero-initialized at load; no runtime allocation) ----
__device__ float4 g_pre[(size_t)NA * CAP];      // per edge: hx,hy,hz, bits(spc|ir|ifr)
// table row (256B stride): [0:32) = 8r x float4 (k=0..3), [32:48) = 8r x float2 (k=4,5)
__device__ float  g_tbl[(TBL_N + 1) * 64];
__device__ int    g_cursor[NA];                 // starts 0; k_atom_mlp resets to 0 each call

__device__ __forceinline__ float silu(float x) { return x / (1.0f + __expf(-x)); }

// ---- pass 1: edge blocks (0..2499) + table blocks (2500..2756) in one grid ----
__global__ __launch_bounds__(128) void k_edge_tbl(
    const float* __restrict__ rij, const int* __restrict__ species,
    const int* __restrict__ fa, const int* __restrict__ sa,
    const float* __restrict__ Wr1, const float* __restrict__ br1,
    const float* __restrict__ Wr2, const float* __restrict__ br2)
{
    int t = threadIdx.x;

    if (blockIdx.x >= EDGE_BLOCKS) {
        // ---- table build: 2 rows per block, 64 threads per row ----
        __shared__ float sh[2][64];
        int b = blockIdx.x - EDGE_BLOCKS;
        int half = t >> 6, i = t & 63;
        int idx = b * 2 + half;
        bool ok = (idx <= TBL_N);
        float fc = 0.f, h = 0.f;
        if (ok) {
            float d = idx * (RCV / TBL_N);
            float dd = fmaxf(d, 1e-6f);
            fc = 0.5f * (cosf(PIF * d * (1.0f / RCV)) + 1.0f);
            float a1 = PIF * dd * (1.0f / RCV);
            float s1, c1;
            sincosf(a1, &s1, &c1);
            float pref = sqrtf(2.0f / RCV) / dd;
            float bes[8];
            float prev = 0.0f, cur = s1, twoc = 2.0f * c1;
            bes[0] = cur * pref;
#pragma unroll
            for (int k = 1; k < 8; k++) { float nxt = twoc * cur - prev; bes[k] = nxt * pref; prev = cur; cur = nxt; }
            h = br1[i];
#pragma unroll
            for (int k = 0; k < 8; k++) h = fmaf(bes[k], __ldg(&Wr1[k * 64 + i]), h);
            h = silu(h);
        }
        sh[half][i] = h;
        __syncthreads();
        if (ok && i < 48) {
            float acc = br2[i];
            const float* hh = sh[half];
#pragma unroll 8
            for (int k = 0; k < 64; k++) acc = fmaf(hh[k], __ldg(&Wr2[k * 48 + i]), acc);
            // output j = 8k+r: k<4 -> idx*64 + r*4 + k ; k>=4 -> idx*64 + 32 + r*2 + (k-4)
            int rr = i & 7, kk = i >> 3;
            int off = (kk < 4) ? (rr * 4 + kk) : (32 + rr * 2 + (kk - 4));
            g_tbl[(size_t)idx * 64 + off] = silu(acc) * fc;
        }
        return;
    }

    // ---- edge path: 16B payload with integer-packed (spc, ir, ifr) ----
    int e = blockIdx.x * 128 + t;
    float x = rij[3 * e + 0], y = rij[3 * e + 1], z = rij[3 * e + 2];
    float d = sqrtf(x * x + y * y + z * z + 1e-12f);
    float inv = 1.0f / d;
    float u = d * ((float)TBL_N / RCV);
    int ir = min((int)u, TBL_N - 1);
    float fr = u - (float)ir;
    int ifr = (int)(fr * 1024.0f);
    if (ifr > 1023) ifr = 1023;
    int spc = species[sa[e]];
    unsigned bits = ((unsigned)spc << 20) | ((unsigned)ir << 10) | (unsigned)ifr;
    int a = fa[e];
    int row = a * CAP + atomicAdd(&g_cursor[a], 1);
    g_pre[row] = make_float4(x * inv, y * inv, z * inv, __uint_as_float(bits));
}

// ---- pass 2: persistent 592 CTAs, static-stride batches; warp-per-atom; batched MLP ----
__global__ __launch_bounds__(256, 4) void k_atom_mlp(
    const float* __restrict__ Wa1, const float* __restrict__ ba1,
    const float* __restrict__ Wa2, const float* __restrict__ ba2,
    const float* __restrict__ Wa3, const float* __restrict__ ba3,
    const float* __restrict__ Ws1, const float* __restrict__ bs1,
    const float* __restrict__ Ws2, const float* __restrict__ bs2,
    float* __restrict__ out)
{
    __shared__ __align__(16) float sfeat[8][192];
    __shared__ __align__(16) float sh1[8][64];
    __shared__ float sW2[4096];
    __shared__ float sW3[64], sB1[64], sB2[64];
    __shared__ float sem[12];
    __shared__ float spart[4][4];

    int t = threadIdx.x, warp = t >> 5, lane = t & 31;
    for (int i = t; i < 4096; i += 256) sW2[i] = Wa2[i];
    if (t < 64) { sW3[t] = Wa3[t]; sB1[t] = ba1[t]; sB2[t] = ba2[t]; }
    if (t < 12) {   // species embedding: 3 species x 4 outputs
        int spq = t >> 2, so = t & 3;
        float a = bs2[so];
#pragma unroll
        for (int i = 0; i < 16; i++)
            a = fmaf(tanhf(Ws1[spq * 16 + i] + bs1[i]), Ws2[i * 4 + so], a);
        sem[t] = a;
    }
    __syncthreads();

    int r = lane & 7, s = lane >> 3;
    float se0 = sem[s], se1 = sem[4 + s], se2 = sem[8 + s];

    for (int nb = blockIdx.x * 8; nb < NA; nb += ATOM_CTAS * 8) {
        __syncthreads();                    // previous batch's MLP reads done

        int n = nb + warp;
        int cnt = g_cursor[n];
        if (lane == 0) g_cursor[n] = 0;     // reset for next graph replay
        float acc[35];
#pragma unroll
        for (int c = 0; c < 35; c++) acc[c] = 0.f;
        float lin = 0.f;
        const float4* base = g_pre + (size_t)n * CAP;

        float4 va[2];
#pragma unroll
        for (int q = 0; q < 2; q++)
            va[q] = (q < cnt) ? __ldg(base + q) : make_float4(0.f, 0.f, 0.f, 0.f);

        for (int i = 0; i < cnt; i++) {
            float4 p = va[i & 1];
            if (i + 2 < cnt) va[i & 1] = __ldg(base + i + 2);

            // cheap integer decode
            unsigned w = __float_as_uint(p.w);
            int spc = (int)(w >> 20);
            int ir = (int)((w >> 10) & 1023u);
            float fr = (float)(w & 1023u) * (1.0f / 1024.0f);
            const float* t0 = g_tbl + (size_t)ir * 64;
            float4 ta4 = *(const float4*)(t0 + 4 * r);
            float2 ta2 = *(const float2*)(t0 + 32 + 2 * r);
            float4 tb4 = *(const float4*)(t0 + 64 + 4 * r);
            float2 tb2 = *(const float2*)(t0 + 96 + 2 * r);
            float sj = (spc == 0) ? se0 : ((spc == 1) ? se1 : se2);

            float F0 = fmaf(fr, tb4.x - ta4.x, ta4.x);
            float F1 = fmaf(fr, tb4.y - ta4.y, ta4.y);
            float F2 = fmaf(fr, tb4.z - ta4.z, ta4.z);
            float F3 = fmaf(fr, tb4.w - ta4.w, ta4.w);
            float F4 = fmaf(fr, tb2.x - ta2.x, ta2.x);
            float F5 = fmaf(fr, tb2.y - ta2.y, ta2.y);

            float hx = p.x, hy = p.y, hz = p.z;
            lin = fmaf(F0, sj, lin);
            float m0 = F1 * sj, m1 = F2 * sj, m2 = F3 * sj, m3 = F4 * sj, m4 = F5 * sj;

            float zz = hz * hz, yz = hy * hz, yy = hy * hy, xz = hx * hz, xy = hx * hy, xx = hx * hx;
            float z3 = hz * zz, yz2 = hy * zz, y2z = yy * hz, y3 = hy * yy,
                  xz2 = hx * zz, xyz = hx * yz, xy2 = hx * yy, x2z = xx * hz, x2y = xx * hy, x3 = hx * xx;
            acc[0]  = fmaf(m0, 1.f, acc[0]);
            acc[1]  = fmaf(m1, hz, acc[1]);  acc[2]  = fmaf(m1, hy, acc[2]);  acc[3]  = fmaf(m1, hx, acc[3]);
            acc[4]  = fmaf(m2, zz, acc[4]);  acc[5]  = fmaf(m2, yz, acc[5]);  acc[6]  = fmaf(m2, yy, acc[6]);
            acc[7]  = fmaf(m2, xz, acc[7]);  acc[8]  = fmaf(m2, xy, acc[8]);  acc[9]  = fmaf(m2, xx, acc[9]);
            acc[10] = fmaf(m3, z3, acc[10]);  acc[11] = fmaf(m3, yz2, acc[11]);
            acc[12] = fmaf(m3, y2z, acc[12]); acc[13] = fmaf(m3, y3, acc[13]);
            acc[14] = fmaf(m3, xz2, acc[14]); acc[15] = fmaf(m3, xyz, acc[15]);
            acc[16] = fmaf(m3, xy2, acc[16]); acc[17] = fmaf(m3, x2z, acc[17]);
            acc[18] = fmaf(m3, x2y, acc[18]); acc[19] = fmaf(m3, x3, acc[19]);
            acc[20] = fmaf(m4, hz * z3, acc[20]);  acc[21] = fmaf(m4, hy * z3, acc[21]);
            acc[22] = fmaf(m4, yy * zz, acc[22]);  acc[23] = fmaf(m4, y3 * hz, acc[23]);
            acc[24] = fmaf(m4, hy * y3, acc[24]);  acc[25] = fmaf(m4, hx * z3, acc[25]);
            acc[26] = fmaf(m4, hx * yz2, acc[26]); acc[27] = fmaf(m4, hx * y2z, acc[27]);
            acc[28] = fmaf(m4, hx * y3, acc[28]);  acc[29] = fmaf(m4, xx * zz, acc[29]);
            acc[30] = fmaf(m4, xx * yz, acc[30]);  acc[31] = fmaf(m4, xx * yy, acc[31]);
            acc[32] = fmaf(m4, x3 * hz, acc[32]);  acc[33] = fmaf(m4, x3 * hy, acc[33]);
            acc[34] = fmaf(m4, hx * x3, acc[34]);
        }

        // contract squared moments into feat[192] (per-warp smem)
        float* sf = sfeat[warp];
        sf[r * 4 + s] = lin;
        sf[(8 + r) * 4 + s] = acc[0] * acc[0];
        sf[(16 + r) * 4 + s] = acc[1] * acc[1] + acc[2] * acc[2] + acc[3] * acc[3];
        sf[(24 + r) * 4 + s] = acc[4] * acc[4] + 2.f * acc[5] * acc[5] + acc[6] * acc[6]
                             + 2.f * acc[7] * acc[7] + 2.f * acc[8] * acc[8] + acc[9] * acc[9];
        const float nm3[10] = {1, 3, 3, 1, 3, 6, 3, 3, 3, 1};
        float f3 = 0.f;
#pragma unroll
        for (int c = 0; c < 10; c++) f3 += nm3[c] * acc[10 + c] * acc[10 + c];
        sf[(32 + r) * 4 + s] = f3;
        const float nm4[15] = {1, 4, 6, 4, 1, 4, 12, 12, 4, 6, 12, 6, 4, 4, 1};
        float f4 = 0.f;
#pragma unroll
        for (int c = 0; c < 15; c++) f4 += nm4[c] * acc[20 + c] * acc[20 + c];
        sf[(40 + r) * 4 + s] = f4;
        __syncthreads();

        // ---- CTA-batched MLP: threads 0-127; group g=t>>6 owns atoms 4g..4g+3 ----
        if (t < 128) {
            int j = t & 63, g = t >> 6;
            int a0 = 4 * g;
            float b1 = sB1[j];
            float h0 = b1, h1 = b1, h2 = b1, h3 = b1;
            const float4* fa4 = (const float4*)sfeat[a0 + 0];
            const float4* fb4 = (const float4*)sfeat[a0 + 1];
            const float4* fc4 = (const float4*)sfeat[a0 + 2];
            const float4* fd4 = (const float4*)sfeat[a0 + 3];
#pragma unroll 2
            for (int f4i = 0; f4i < 48; f4i++) {
                float4 qa = fa4[f4i], qb = fb4[f4i], qc = fc4[f4i], qd = fd4[f4i];
                int fb = f4i * 4;
                float w0 = __ldg(&Wa1[(fb + 0) * 64 + j]);
                float w1 = __ldg(&Wa1[(fb + 1) * 64 + j]);
                float w2 = __ldg(&Wa1[(fb + 2) * 64 + j]);
                float w3 = __ldg(&Wa1[(fb + 3) * 64 + j]);
                h0 = fmaf(qa.x, w0, h0); h1 = fmaf(qb.x, w0, h1); h2 = fmaf(qc.x, w0, h2); h3 = fmaf(qd.x, w0, h3);
                h0 = fmaf(qa.y, w1, h0); h1 = fmaf(qb.y, w1, h1); h2 = fmaf(qc.y, w1, h2); h3 = fmaf(qd.y, w1, h3);
                h0 = fmaf(qa.z, w2, h0); h1 = fmaf(qb.z, w2, h1); h2 = fmaf(qc.z, w2, h2); h3 = fmaf(qd.z, w2, h3);
                h0 = fmaf(qa.w, w3, h0); h1 = fmaf(qb.w, w3, h1); h2 = fmaf(qc.w, w3, h2); h3 = fmaf(qd.w, w3, h3);
            }
            sh1[a0 + 0][j] = silu(h0);
            sh1[a0 + 1][j] = silu(h1);
            sh1[a0 + 2][j] = silu(h2);
            sh1[a0 + 3][j] = silu(h3);
        }
        __syncthreads();

        if (t < 128) {
            int j = t & 63, g = t >> 6;
            int a0 = 4 * g;
            float b2 = sB2[j];
            float g0 = b2, g1 = b2, g2 = b2, g3 = b2;
            const float4* ha4 = (const float4*)sh1[a0 + 0];
            const float4* hb4 = (const float4*)sh1[a0 + 1];
            const float4* hc4 = (const float4*)sh1[a0 + 2];
            const float4* hd4 = (const float4*)sh1[a0 + 3];
#pragma unroll 2
            for (int k4 = 0; k4 < 16; k4++) {
                float4 qa = ha4[k4], qb = hb4[k4], qc = hc4[k4], qd = hd4[k4];
                int kb = k4 * 4;
                float w0 = sW2[(kb + 0) * 64 + j];
                float w1 = sW2[(kb + 1) * 64 + j];
                float w2 = sW2[(kb + 2) * 64 + j];
                float w3 = sW2[(kb + 3) * 64 + j];
                g0 = fmaf(qa.x, w0, g0); g1 = fmaf(qb.x, w0, g1); g2 = fmaf(qc.x, w0, g2); g3 = fmaf(qd.x, w0, g3);
                g0 = fmaf(qa.y, w1, g0); g1 = fmaf(qb.y, w1, g1); g2 = fmaf(qc.y, w1, g2); g3 = fmaf(qd.y, w1, g3);
                g0 = fmaf(qa.z, w2, g0); g1 = fmaf(qb.z, w2, g1); g2 = fmaf(qc.z, w2, g2); g3 = fmaf(qd.z, w2, g3);
                g0 = fmaf(qa.w, w3, g0); g1 = fmaf(qb.w, w3, g1); g2 = fmaf(qc.w, w3, g2); g3 = fmaf(qd.w, w3, g3);
            }
            float w3j = sW3[j];
            float p0 = silu(g0) * w3j, p1 = silu(g1) * w3j, p2 = silu(g2) * w3j, p3 = silu(g3) * w3j;
#pragma unroll
            for (int off = 16; off; off >>= 1) {
                p0 += __shfl_down_sync(0xffffffffu, p0, off);
                p1 += __shfl_down_sync(0xffffffffu, p1, off);
                p2 += __shfl_down_sync(0xffffffffu, p2, off);
                p3 += __shfl_down_sync(0xffffffffu, p3, off);
            }
            if (lane == 0) {
                spart[warp][0] = p0; spart[warp][1] = p1;
                spart[warp][2] = p2; spart[warp][3] = p3;
            }
        }
        __syncthreads();
        if (t < 8)
            out[nb + t] = spart[(t >> 2) * 2][t & 3]
                        + spart[(t >> 2) * 2 + 1][t & 3] + ba3[0];
    }
}

extern "C" void kernel_launch(void* const* d_in, const int* in_sizes, int n_in,
                              void* d_out, int out_size) {
    const float* rij = (const float*)d_in[0];
    const int* species = (const int*)d_in[1];
    const int* fa = (const int*)d_in[2];
    const int* sa = (const int*)d_in[3];
    const float* Wr1 = (const float*)d_in[4];
    const float* br1 = (const float*)d_in[5];
    const float* Wr2 = (const float*)d_in[6];
    const float* br2 = (const float*)d_in[7];
    const float* Ws1 = (const float*)d_in[8];
    const float* bs1 = (const float*)d_in[9];
    const float* Ws2 = (const float*)d_in[10];
    const float* bs2 = (const float*)d_in[11];
    const float* Wa1 = (const float*)d_in[12];
    const float* ba1 = (const float*)d_in[13];
    const float* Wa2 = (const float*)d_in[14];
    const float* ba2 = (const float*)d_in[15];
    const float* Wa3 = (const float*)d_in[16];
    const float* ba3 = (const float*)d_in[17];
    float* out = (float*)d_out;

    k_edge_tbl<<<EDGE_BLOCKS + TBL_BLOCKS, 128>>>(rij, species, fa, sa,
                                                  Wr1, br1, Wr2, br2);
    k_atom_mlp<<<ATOM_CTAS, 256>>>(Wa1, ba1, Wa2, ba2, Wa3, ba3,
                                   Ws1, bs1, Ws2, bs2, out);
}

// round 17
// speedup vs baseline: 1.2512x; 1.0849x over previous
#include <cuda_runtime.h>
#include <stdint.h>
#include <math.h>

#define NE 320000
#define NA 10000
#define CAP 128            // per-atom bin capacity (P(deg>128) ~ e^-81)
#define RCV 5.0f
#define TBL_N 512
#define PIF 3.14159265358979323846f
#define EDGE_BLOCKS (NE / 128)     // 2500
#define TBL_BLOCKS 257             // 2 rows per block -> 514 >= 513

// ---- scratch (device globals; zero-initialized at load; no runtime allocation) ----
__device__ float4 g_pre[(size_t)NA * CAP];      // per edge: hx,hy,hz, bits(spc|ir|ifr)
// table row (256B stride): [0:32) = 8r x float4 (k=0..3), [32:48) = 8r x float2 (k=4,5)
__device__ float  g_tbl[(TBL_N + 1) * 64];
__device__ float  g_feat[(size_t)NA * 192];
__device__ float  g_sem[12];
__device__ int    g_cursor[NA];                 // starts 0; k_acc resets to 0 each call

__device__ __forceinline__ float silu(float x) { return x / (1.0f + __expf(-x)); }

// ---- pass 1: edge blocks (0..2499) + table blocks (2500..2756) in one grid ----
__global__ __launch_bounds__(128) void k_edge_tbl(
    const float* __restrict__ rij, const int* __restrict__ species,
    const int* __restrict__ fa, const int* __restrict__ sa,
    const float* __restrict__ Wr1, const float* __restrict__ br1,
    const float* __restrict__ Wr2, const float* __restrict__ br2,
    const float* __restrict__ Ws1, const float* __restrict__ bs1,
    const float* __restrict__ Ws2, const float* __restrict__ bs2)
{
    int t = threadIdx.x;

    if (blockIdx.x >= EDGE_BLOCKS) {
        // ---- species embedding (block EDGE_BLOCKS only, lanes 0..11) ----
        if (blockIdx.x == EDGE_BLOCKS && t >= 64 && t < 76) {
            int tt = t - 64;
            int spq = tt >> 2, so = tt & 3;
            float a = bs2[so];
#pragma unroll
            for (int i = 0; i < 16; i++)
                a = fmaf(tanhf(Ws1[spq * 16 + i] + bs1[i]), Ws2[i * 4 + so], a);
            g_sem[tt] = a;
        }
        // ---- table build: 2 rows per block, 64 threads per row ----
        __shared__ float sh[2][64];
        int b = blockIdx.x - EDGE_BLOCKS;
        int half = t >> 6, i = t & 63;
        int idx = b * 2 + half;
        bool ok = (idx <= TBL_N);
        float fc = 0.f, h = 0.f;
        if (ok) {
            float d = idx * (RCV / TBL_N);
            float dd = fmaxf(d, 1e-6f);
            fc = 0.5f * (cosf(PIF * d * (1.0f / RCV)) + 1.0f);
            float a1 = PIF * dd * (1.0f / RCV);
            float s1, c1;
            sincosf(a1, &s1, &c1);
            float pref = sqrtf(2.0f / RCV) / dd;
            float bes[8];
            float prev = 0.0f, cur = s1, twoc = 2.0f * c1;
            bes[0] = cur * pref;
#pragma unroll
            for (int k = 1; k < 8; k++) { float nxt = twoc * cur - prev; bes[k] = nxt * pref; prev = cur; cur = nxt; }
            h = br1[i];
#pragma unroll
            for (int k = 0; k < 8; k++) h = fmaf(bes[k], __ldg(&Wr1[k * 64 + i]), h);
            h = silu(h);
        }
        sh[half][i] = h;
        __syncthreads();
        if (ok && i < 48) {
            float acc = br2[i];
            const float* hh = sh[half];
#pragma unroll 8
            for (int k = 0; k < 64; k++) acc = fmaf(hh[k], __ldg(&Wr2[k * 48 + i]), acc);
            // output j = 8k+r: k<4 -> idx*64 + r*4 + k ; k>=4 -> idx*64 + 32 + r*2 + (k-4)
            int rr = i & 7, kk = i >> 3;
            int off = (kk < 4) ? (rr * 4 + kk) : (32 + rr * 2 + (kk - 4));
            g_tbl[(size_t)idx * 64 + off] = silu(acc) * fc;
        }
        return;
    }

    // ---- edge path: 16B payload with integer-packed (spc, ir, ifr) ----
    int e = blockIdx.x * 128 + t;
    float x = rij[3 * e + 0], y = rij[3 * e + 1], z = rij[3 * e + 2];
    float d = sqrtf(x * x + y * y + z * z + 1e-12f);
    float inv = 1.0f / d;
    float u = d * ((float)TBL_N / RCV);
    int ir = min((int)u, TBL_N - 1);
    float fr = u - (float)ir;
    int ifr = (int)(fr * 1024.0f);
    if (ifr > 1023) ifr = 1023;
    int spc = species[sa[e]];
    unsigned bits = ((unsigned)spc << 20) | ((unsigned)ir << 10) | (unsigned)ifr;
    int a = fa[e];
    int row = a * CAP + atomicAdd(&g_cursor[a], 1);
    g_pre[row] = make_float4(x * inv, y * inv, z * inv, __uint_as_float(bits));
}

// ---- pass 2: warp-sized CTAs, one atom each — zero cross-warp coupling ----
__global__ __launch_bounds__(32, 28) void k_acc()
{
    int lane = threadIdx.x;
    int n = blockIdx.x;
    int cnt = g_cursor[n];
    if (lane == 0) g_cursor[n] = 0;          // reset for next graph replay
    int r = lane & 7, s = lane >> 3;
    float se0 = __ldg(&g_sem[s]), se1 = __ldg(&g_sem[4 + s]), se2 = __ldg(&g_sem[8 + s]);
    float acc[35];
#pragma unroll
    for (int c = 0; c < 35; c++) acc[c] = 0.f;
    float lin = 0.f;
    const float4* base = g_pre + (size_t)n * CAP;

    float4 va[2];
#pragma unroll
    for (int q = 0; q < 2; q++)
        va[q] = (q < cnt) ? __ldg(base + q) : make_float4(0.f, 0.f, 0.f, 0.f);

    for (int i = 0; i < cnt; i++) {
        float4 p = va[i & 1];
        if (i + 2 < cnt) va[i & 1] = __ldg(base + i + 2);

        // cheap integer decode
        unsigned w = __float_as_uint(p.w);
        int spc = (int)(w >> 20);
        int ir = (int)((w >> 10) & 1023u);
        float fr = (float)(w & 1023u) * (1.0f / 1024.0f);
        const float* t0 = g_tbl + (size_t)ir * 64;
        float4 ta4 = *(const float4*)(t0 + 4 * r);
        float2 ta2 = *(const float2*)(t0 + 32 + 2 * r);
        float4 tb4 = *(const float4*)(t0 + 64 + 4 * r);
        float2 tb2 = *(const float2*)(t0 + 96 + 2 * r);
        float sj = (spc == 0) ? se0 : ((spc == 1) ? se1 : se2);

        float F0 = fmaf(fr, tb4.x - ta4.x, ta4.x);
        float F1 = fmaf(fr, tb4.y - ta4.y, ta4.y);
        float F2 = fmaf(fr, tb4.z - ta4.z, ta4.z);
        float F3 = fmaf(fr, tb4.w - ta4.w, ta4.w);
        float F4 = fmaf(fr, tb2.x - ta2.x, ta2.x);
        float F5 = fmaf(fr, tb2.y - ta2.y, ta2.y);

        float hx = p.x, hy = p.y, hz = p.z;
        lin = fmaf(F0, sj, lin);
        float m0 = F1 * sj, m1 = F2 * sj, m2 = F3 * sj, m3 = F4 * sj, m4 = F5 * sj;

        float zz = hz * hz, yz = hy * hz, yy = hy * hy, xz = hx * hz, xy = hx * hy, xx = hx * hx;
        float z3 = hz * zz, yz2 = hy * zz, y2z = yy * hz, y3 = hy * yy,
              xz2 = hx * zz, xyz = hx * yz, xy2 = hx * yy, x2z = xx * hz, x2y = xx * hy, x3 = hx * xx;
        acc[0]  = fmaf(m0, 1.f, acc[0]);
        acc[1]  = fmaf(m1, hz, acc[1]);  acc[2]  = fmaf(m1, hy, acc[2]);  acc[3]  = fmaf(m1, hx, acc[3]);
        acc[4]  = fmaf(m2, zz, acc[4]);  acc[5]  = fmaf(m2, yz, acc[5]);  acc[6]  = fmaf(m2, yy, acc[6]);
        acc[7]  = fmaf(m2, xz, acc[7]);  acc[8]  = fmaf(m2, xy, acc[8]);  acc[9]  = fmaf(m2, xx, acc[9]);
        acc[10] = fmaf(m3, z3, acc[10]);  acc[11] = fmaf(m3, yz2, acc[11]);
        acc[12] = fmaf(m3, y2z, acc[12]); acc[13] = fmaf(m3, y3, acc[13]);
        acc[14] = fmaf(m3, xz2, acc[14]); acc[15] = fmaf(m3, xyz, acc[15]);
        acc[16] = fmaf(m3, xy2, acc[16]); acc[17] = fmaf(m3, x2z, acc[17]);
        acc[18] = fmaf(m3, x2y, acc[18]); acc[19] = fmaf(m3, x3, acc[19]);
        acc[20] = fmaf(m4, hz * z3, acc[20]);  acc[21] = fmaf(m4, hy * z3, acc[21]);
        acc[22] = fmaf(m4, yy * zz, acc[22]);  acc[23] = fmaf(m4, y3 * hz, acc[23]);
        acc[24] = fmaf(m4, hy * y3, acc[24]);  acc[25] = fmaf(m4, hx * z3, acc[25]);
        acc[26] = fmaf(m4, hx * yz2, acc[26]); acc[27] = fmaf(m4, hx * y2z, acc[27]);
        acc[28] = fmaf(m4, hx * y3, acc[28]);  acc[29] = fmaf(m4, xx * zz, acc[29]);
        acc[30] = fmaf(m4, xx * yz, acc[30]);  acc[31] = fmaf(m4, xx * yy, acc[31]);
        acc[32] = fmaf(m4, x3 * hz, acc[32]);  acc[33] = fmaf(m4, x3 * hy, acc[33]);
        acc[34] = fmaf(m4, hx * x3, acc[34]);
    }

    // contract squared moments; each store is a coalesced 128B line
    float* fo = g_feat + (size_t)n * 192;
    int o = r * 4 + s;                    // permutation of 0..31 across the warp
    fo[o] = lin;
    fo[32 + o] = acc[0] * acc[0];
    fo[64 + o] = acc[1] * acc[1] + acc[2] * acc[2] + acc[3] * acc[3];
    fo[96 + o] = acc[4] * acc[4] + 2.f * acc[5] * acc[5] + acc[6] * acc[6]
               + 2.f * acc[7] * acc[7] + 2.f * acc[8] * acc[8] + acc[9] * acc[9];
    const float nm3[10] = {1, 3, 3, 1, 3, 6, 3, 3, 3, 1};
    float f3 = 0.f;
#pragma unroll
    for (int c = 0; c < 10; c++) f3 += nm3[c] * acc[10 + c] * acc[10 + c];
    fo[128 + o] = f3;
    const float nm4[15] = {1, 4, 6, 4, 1, 4, 12, 12, 4, 6, 12, 6, 4, 4, 1};
    float f4 = 0.f;
#pragma unroll
    for (int c = 0; c < 15; c++) f4 += nm4[c] * acc[20 + c] * acc[20 + c];
    fo[160 + o] = f4;
}

// ---- pass 3: batched MLP, 8 atoms per 256-thread CTA ----
__global__ __launch_bounds__(256, 4) void k_mlp(
    const float* __restrict__ Wa1, const float* __restrict__ ba1,
    const float* __restrict__ Wa2, const float* __restrict__ ba2,
    const float* __restrict__ Wa3, const float* __restrict__ ba3,
    float* __restrict__ out)
{
    __shared__ __align__(16) float sfeat[8][192];
    __shared__ __align__(16) float sh1[8][64];
    __shared__ float sW2[4096];
    __shared__ float sW3[64], sB1[64], sB2[64];
    __shared__ float spart[4][4];

    int t = threadIdx.x, warp = t >> 5, lane = t & 31;
    for (int i = t; i < 4096; i += 256) sW2[i] = Wa2[i];
    if (t < 64) { sW3[t] = Wa3[t]; sB1[t] = ba1[t]; sB2[t] = ba2[t]; }
    // stage feats: 1536 floats = 384 float4, coalesced
    {
        const float4* src = (const float4*)(g_feat + (size_t)blockIdx.x * 8 * 192);
        float4* dst = (float4*)&sfeat[0][0];
#pragma unroll
        for (int i = t; i < 384; i += 256) dst[i] = __ldg(src + i);
    }
    __syncthreads();

    if (t < 128) {
        int j = t & 63, g = t >> 6;
        int a0 = 4 * g;
        float b1 = sB1[j];
        float h0 = b1, h1 = b1, h2 = b1, h3 = b1;
        const float4* fa4 = (const float4*)sfeat[a0 + 0];
        const float4* fb4 = (const float4*)sfeat[a0 + 1];
        const float4* fc4 = (const float4*)sfeat[a0 + 2];
        const float4* fd4 = (const float4*)sfeat[a0 + 3];
#pragma unroll 2
        for (int f4i = 0; f4i < 48; f4i++) {
            float4 qa = fa4[f4i], qb = fb4[f4i], qc = fc4[f4i], qd = fd4[f4i];
            int fb = f4i * 4;
            float w0 = __ldg(&Wa1[(fb + 0) * 64 + j]);
            float w1 = __ldg(&Wa1[(fb + 1) * 64 + j]);
            float w2 = __ldg(&Wa1[(fb + 2) * 64 + j]);
            float w3 = __ldg(&Wa1[(fb + 3) * 64 + j]);
            h0 = fmaf(qa.x, w0, h0); h1 = fmaf(qb.x, w0, h1); h2 = fmaf(qc.x, w0, h2); h3 = fmaf(qd.x, w0, h3);
            h0 = fmaf(qa.y, w1, h0); h1 = fmaf(qb.y, w1, h1); h2 = fmaf(qc.y, w1, h2); h3 = fmaf(qd.y, w1, h3);
            h0 = fmaf(qa.z, w2, h0); h1 = fmaf(qb.z, w2, h1); h2 = fmaf(qc.z, w2, h2); h3 = fmaf(qd.z, w2, h3);
            h0 = fmaf(qa.w, w3, h0); h1 = fmaf(qb.w, w3, h1); h2 = fmaf(qc.w, w3, h2); h3 = fmaf(qd.w, w3, h3);
        }
        sh1[a0 + 0][j] = silu(h0);
        sh1[a0 + 1][j] = silu(h1);
        sh1[a0 + 2][j] = silu(h2);
        sh1[a0 + 3][j] = silu(h3);
    }
    __syncthreads();

    if (t < 128) {
        int j = t & 63, g = t >> 6;
        int a0 = 4 * g;
        float b2 = sB2[j];
        float g0 = b2, g1 = b2, g2 = b2, g3 = b2;
        const float4* ha4 = (const float4*)sh1[a0 + 0];
        const float4* hb4 = (const float4*)sh1[a0 + 1];
        const float4* hc4 = (const float4*)sh1[a0 + 2];
        const float4* hd4 = (const float4*)sh1[a0 + 3];
#pragma unroll 2
        for (int k4 = 0; k4 < 16; k4++) {
            float4 qa = ha4[k4], qb = hb4[k4], qc = hc4[k4], qd = hd4[k4];
            int kb = k4 * 4;
            float w0 = sW2[(kb + 0) * 64 + j];
            float w1 = sW2[(kb + 1) * 64 + j];
            float w2 = sW2[(kb + 2) * 64 + j];
            float w3 = sW2[(kb + 3) * 64 + j];
            g0 = fmaf(qa.x, w0, g0); g1 = fmaf(qb.x, w0, g1); g2 = fmaf(qc.x, w0, g2); g3 = fmaf(qd.x, w0, g3);
            g0 = fmaf(qa.y, w1, g0); g1 = fmaf(qb.y, w1, g1); g2 = fmaf(qc.y, w1, g2); g3 = fmaf(qd.y, w1, g3);
            g0 = fmaf(qa.z, w2, g0); g1 = fmaf(qb.z, w2, g1); g2 = fmaf(qc.z, w2, g2); g3 = fmaf(qd.z, w2, g3);
            g0 = fmaf(qa.w, w3, g0); g1 = fmaf(qb.w, w3, g1); g2 = fmaf(qc.w, w3, g2); g3 = fmaf(qd.w, w3, g3);
        }
        float w3j = sW3[j];
        float p0 = silu(g0) * w3j, p1 = silu(g1) * w3j, p2 = silu(g2) * w3j, p3 = silu(g3) * w3j;
#pragma unroll
        for (int off = 16; off; off >>= 1) {
            p0 += __shfl_down_sync(0xffffffffu, p0, off);
            p1 += __shfl_down_sync(0xffffffffu, p1, off);
            p2 += __shfl_down_sync(0xffffffffu, p2, off);
            p3 += __shfl_down_sync(0xffffffffu, p3, off);
        }
        if (lane == 0) {
            spart[warp][0] = p0; spart[warp][1] = p1;
            spart[warp][2] = p2; spart[warp][3] = p3;
        }
    }
    __syncthreads();
    if (t < 8)
        out[blockIdx.x * 8 + t] = spart[(t >> 2) * 2][t & 3]
                                + spart[(t >> 2) * 2 + 1][t & 3] + ba3[0];
}

extern "C" void kernel_launch(void* const* d_in, const int* in_sizes, int n_in,
                              void* d_out, int out_size) {
    const float* rij = (const float*)d_in[0];
    const int* species = (const int*)d_in[1];
    const int* fa = (const int*)d_in[2];
    const int* sa = (const int*)d_in[3];
    const float* Wr1 = (const float*)d_in[4];
    const float* br1 = (const float*)d_in[5];
    const float* Wr2 = (const float*)d_in[6];
    const float* br2 = (const float*)d_in[7];
    const float* Ws1 = (const float*)d_in[8];
    const float* bs1 = (const float*)d_in[9];
    const float* Ws2 = (const float*)d_in[10];
    const float* bs2 = (const float*)d_in[11];
    const float* Wa1 = (const float*)d_in[12];
    const float* ba1 = (const float*)d_in[13];
    const float* Wa2 = (const float*)d_in[14];
    const float* ba2 = (const float*)d_in[15];
    const float* Wa3 = (const float*)d_in[16];
    const float* ba3 = (const float*)d_in[17];
    float* out = (float*)d_out;

    k_edge_tbl<<<EDGE_BLOCKS + TBL_BLOCKS, 128>>>(rij, species, fa, sa,
                                                  Wr1, br1, Wr2, br2,
                                                  Ws1, bs1, Ws2, bs2);
    k_acc<<<NA, 32>>>();
    k_mlp<<<NA / 8, 256>>>(Wa1, ba1, Wa2, ba2, Wa3, ba3, out);
}